// round 5
// baseline (speedup 1.0000x reference)
#include <cuda_runtime.h>
#include <math.h>

#define BB 4
#define CC 128
#define NBOX 4
#define BTC 32
#define HH 256
#define WW 256
#define HWSZ (HH*WW)
#define SW 257                      // integral image row stride

// scratch (static device globals; no dynamic allocation)
__device__ float g_z[BB*BTC*HH*WW];       // ROW-SCANNED z = rowcumsum(BN1(conv))
__device__ float g_S[BB*BTC*SW*SW];       // 2D integral image, zero borders

// ---------------------------------------------------------------------------
// Kernel 1: z = rowcumsum( BN1(x @ w1^T) )
// block = one image row (b, i): 256 px x 32 channels.
// thread: 4 px x 8 ch. Epilogue does per-channel inclusive scan across the row.
// ---------------------------------------------------------------------------
__global__ __launch_bounds__(256) void k1_conv_bn_rowscan(
    const float* __restrict__ x, const float* __restrict__ w1,
    const float* __restrict__ g1, const float* __restrict__ b1,
    const float* __restrict__ m1, const float* __restrict__ v1)
{
    __shared__ float xs[32][256];
    __shared__ float ws[128][32];
    __shared__ float wtot[8][8];     // [warp][q] warp totals for the scan

    const int tid = threadIdx.x;

    for (int idx = tid; idx < CC*BTC; idx += 256) {
        int k = idx & 31;
        int c = idx >> 5;
        float inv = g1[k] * rsqrtf(v1[k] + 1e-5f);
        ws[c][k] = w1[k*CC + c] * inv;
    }

    const int pixbase = blockIdx.x * 256;    // one row: b, i fixed
    const int b  = pixbase >> 16;
    const int ij = pixbase & 65535;
    const float* xp = x + (size_t)b*CC*HWSZ + ij;

    const int tp = tid & 63;
    const int tk = tid >> 6;

    float acc[4][8];
    #pragma unroll
    for (int p = 0; p < 4; p++)
        #pragma unroll
        for (int q = 0; q < 8; q++) acc[p][q] = 0.f;

    const int cl = tid >> 6;
    const int p4 = (tid & 63) * 4;

    for (int kc = 0; kc < CC; kc += 32) {
        __syncthreads();
        #pragma unroll
        for (int it = 0; it < 8; it++) {
            int c = kc + it*4 + cl;
            float4 v = *(const float4*)(xp + (size_t)c*HWSZ + p4);
            *(float4*)&xs[it*4 + cl][p4] = v;
        }
        __syncthreads();

        #pragma unroll
        for (int c = 0; c < 32; c++) {
            float4 xv = *(float4*)&xs[c][tp*4];
            float4 wa = *(float4*)&ws[kc + c][tk*8];
            float4 wb = *(float4*)&ws[kc + c][tk*8 + 4];
            float xr[4] = {xv.x, xv.y, xv.z, xv.w};
            float wr[8] = {wa.x, wa.y, wa.z, wa.w, wb.x, wb.y, wb.z, wb.w};
            #pragma unroll
            for (int p = 0; p < 4; p++)
                #pragma unroll
                for (int q = 0; q < 8; q++)
                    acc[p][q] += xr[p] * wr[q];
        }
    }

    // ---- epilogue: bias, then inclusive row scan per channel ----
    const int lane = tid & 31;
    const int wid  = tid >> 5;      // warps 2*tk (tp 0..31), 2*tk+1 (tp 32..63)
    float tot[8];

    #pragma unroll
    for (int q = 0; q < 8; q++) {
        int k = tk*8 + q;
        float inv  = g1[k] * rsqrtf(v1[k] + 1e-5f);
        float bias = b1[k] - m1[k]*inv;
        // local inclusive prefix of the thread's 4 pixels (in place)
        float a0 = acc[0][q] + bias;
        float a1 = acc[1][q] + bias;
        float a2 = acc[2][q] + bias;
        float a3 = acc[3][q] + bias;
        acc[0][q] = a0;
        acc[1][q] = a0 + a1;
        acc[2][q] = acc[1][q] + a2;
        acc[3][q] = acc[2][q] + a3;
        // warp inclusive scan of thread sums
        float s = acc[3][q];
        #pragma unroll
        for (int o = 1; o < 32; o <<= 1) {
            float t = __shfl_up_sync(0xffffffffu, s, o);
            if (lane >= o) s += t;
        }
        tot[q] = s;
        if (lane == 31) wtot[wid][q] = s;
    }
    __syncthreads();

    #pragma unroll
    for (int q = 0; q < 8; q++) {
        int k = tk*8 + q;
        float off = tot[q] - acc[3][q];              // exclusive within warp
        if (wid & 1) off += wtot[wid - 1][q];        // add even-warp total
        float4 r = make_float4(acc[0][q] + off, acc[1][q] + off,
                               acc[2][q] + off, acc[3][q] + off);
        *(float4*)(g_z + (size_t)(b*BTC + k)*HWSZ + ij + tp*4) = r;
    }
}

// ---------------------------------------------------------------------------
// Kernel 2: column cumsum of row-scanned z -> integral image S with zero borders
// one block per plane; thread = column; coalesced rows; serial over 256 rows.
// ---------------------------------------------------------------------------
__global__ __launch_bounds__(256) void k2_colsum_S()
{
    const int plane = blockIdx.x;    // 0..127
    const int j     = threadIdx.x;
    const float* zp = g_z + (size_t)plane*HWSZ + j;
    float* Sp = g_S + (size_t)plane*SW*SW;

    // zero borders: row 0 and column 0
    Sp[j] = 0.f;
    if (j == 0) Sp[256] = 0.f;
    Sp[(size_t)(j+1)*SW] = 0.f;

    float acc = 0.f;
    #pragma unroll 8
    for (int i = 0; i < HH; i++) {
        acc += zp[(size_t)i*WW];
        Sp[(size_t)(i+1)*SW + (j+1)] = acc;
    }
}

// ---------------------------------------------------------------------------
// Kernel 3: separable box filter via shared vertical-difference vector.
// (round-3 version — known 95.6us @ occ 94%)
// ---------------------------------------------------------------------------
__global__ __launch_bounds__(256) void k3_box(
    const float* __restrict__ x,
    const float* __restrict__ xmn_, const float* __restrict__ xmx_,
    const float* __restrict__ ymn_, const float* __restrict__ ymx_,
    const float* __restrict__ g2, const float* __restrict__ b2,
    const float* __restrict__ m2, const float* __restrict__ v2,
    float* __restrict__ out)
{
    __shared__ float Dv[8][SW];     // 8 x 257 floats = 8.2 KB

    const int bid = blockIdx.x;
    const int rc  = bid & 31;                 // row chunk (8 rows)
    const int nb  = (bid >> 5) & (NBOX-1);
    const int bt  = (bid >> 7) & (BTC-1);
    const int b   = bid >> 12;
    const int j   = threadIdx.x;
    const int k   = bt*NBOX + nb;
    const int boxi = bt*NBOX + nb;

    const float xmn = xmn_[boxi], xmx = xmx_[boxi];
    const float ymn = ymn_[boxi], ymx = ymx_[boxi];
    const float inv_area = 1.f / ((xmx - xmn) * (ymx - ymn));

    const float* Sp = g_S + (size_t)(b*BTC + bt)*SW*SW;

    // ---- phase 1: vertical lerp-difference for 8 rows ----
    #pragma unroll
    for (int r = 0; r < 8; r++) {
        int i = rc*8 + r;
        float uA = fminf(fmaxf((float)i + xmx, 0.f), 256.f);
        float uB = fminf(fmaxf((float)i + xmn, 0.f), 256.f);
        float fA = fminf(floorf(uA), 255.f);
        float fB = fminf(floorf(uB), 255.f);
        int   iA = (int)fA, iB = (int)fB;
        float wA = uA - fA, wB = uB - fB;

        const float* RA0 = Sp + (size_t)iA*SW;
        const float* RB0 = Sp + (size_t)iB*SW;

        float d = (RA0[j]*(1.f-wA) + RA0[SW+j]*wA)
                - (RB0[j]*(1.f-wB) + RB0[SW+j]*wB);
        Dv[r][j] = d;
        if (j == 255) {
            float d2 = (RA0[256]*(1.f-wA) + RA0[SW+256]*wA)
                     - (RB0[256]*(1.f-wB) + RB0[SW+256]*wB);
            Dv[r][256] = d2;
        }
    }
    __syncthreads();

    // ---- phase 2: horizontal fractional box from smem ----
    float vA = fminf(fmaxf((float)j + ymx, 0.f), 256.f);
    float vB = fminf(fmaxf((float)j + ymn, 0.f), 256.f);
    float gA = fminf(floorf(vA), 255.f);
    float gB = fminf(floorf(vB), 255.f);
    int   jA = (int)gA, jB = (int)gB;
    float wvA = vA - gA, wvB = vB - gB;

    float inv2  = g2[k] * rsqrtf(v2[k] + 1e-3f);
    float bias2 = b2[k] - m2[k]*inv2;

    const float* xrow = x   + ((size_t)(b*CC + k)*HH + rc*8)*WW + j;
    float*       orow = out + ((size_t)(b*CC + k)*HH + rc*8)*WW + j;

    #pragma unroll
    for (int r = 0; r < 8; r++) {
        float DA = Dv[r][jA]*(1.f - wvA) + Dv[r][jA+1]*wvA;
        float DB = Dv[r][jB]*(1.f - wvB) + Dv[r][jB+1]*wvB;
        float val = (DA - DB) * inv_area;

        val = fmaxf(val*inv2 + bias2, 0.f);
        orow[(size_t)r*WW] = fmaxf(xrow[(size_t)r*WW] + val, 0.f);
    }
}

// ---------------------------------------------------------------------------
extern "C" void kernel_launch(void* const* d_in, const int* in_sizes, int n_in,
                              void* d_out, int out_size)
{
    const float* x    = (const float*)d_in[0];
    const float* w1   = (const float*)d_in[1];
    const float* g1   = (const float*)d_in[2];
    const float* b1   = (const float*)d_in[3];
    const float* m1   = (const float*)d_in[4];
    const float* v1   = (const float*)d_in[5];
    const float* xmn  = (const float*)d_in[6];
    const float* xmx  = (const float*)d_in[7];
    const float* ymn  = (const float*)d_in[8];
    const float* ymx  = (const float*)d_in[9];
    const float* g2   = (const float*)d_in[10];
    const float* b2   = (const float*)d_in[11];
    const float* m2   = (const float*)d_in[12];
    const float* v2   = (const float*)d_in[13];
    float* out = (float*)d_out;

    k1_conv_bn_rowscan<<<(BB*HWSZ)/256, 256>>>(x, w1, g1, b1, m1, v1);
    k2_colsum_S<<<BB*BTC, 256>>>();
    k3_box<<<BB*BTC*NBOX*(HH/8), 256>>>(x, xmn, xmx, ymn, ymx, g2, b2, m2, v2, out);
}

// round 6
// speedup vs baseline: 1.3094x; 1.3094x over previous
#include <cuda_runtime.h>
#include <math.h>

#define BB 4
#define CC 128
#define NBOX 4
#define BTC 32
#define HH 256
#define WW 256
#define HWSZ (HH*WW)
#define SW 257                      // integral image row stride

// scratch (static device globals; no dynamic allocation)
__device__ float g_z[BB*BTC*HH*WW];       // ROW-SCANNED z = rowcumsum(BN1(conv))
__device__ float g_S[BB*BTC*SW*SW];       // 2D integral image, zero borders
__device__ float g_ctot[BB*BTC][4][WW];   // per-chunk column totals

// ---------------------------------------------------------------------------
// Kernel 1: z = rowcumsum( BN1(x @ w1^T) )
// block = one image row (b, i): 256 px x 32 channels.
// ---------------------------------------------------------------------------
__global__ __launch_bounds__(256) void k1_conv_bn_rowscan(
    const float* __restrict__ x, const float* __restrict__ w1,
    const float* __restrict__ g1, const float* __restrict__ b1,
    const float* __restrict__ m1, const float* __restrict__ v1)
{
    __shared__ float xs[32][256];
    __shared__ float ws[128][32];
    __shared__ float wtot[8][8];

    const int tid = threadIdx.x;

    for (int idx = tid; idx < CC*BTC; idx += 256) {
        int k = idx & 31;
        int c = idx >> 5;
        float inv = g1[k] * rsqrtf(v1[k] + 1e-5f);
        ws[c][k] = w1[k*CC + c] * inv;
    }

    const int pixbase = blockIdx.x * 256;
    const int b  = pixbase >> 16;
    const int ij = pixbase & 65535;
    const float* xp = x + (size_t)b*CC*HWSZ + ij;

    const int tp = tid & 63;
    const int tk = tid >> 6;

    float acc[4][8];
    #pragma unroll
    for (int p = 0; p < 4; p++)
        #pragma unroll
        for (int q = 0; q < 8; q++) acc[p][q] = 0.f;

    const int cl = tid >> 6;
    const int p4 = (tid & 63) * 4;

    for (int kc = 0; kc < CC; kc += 32) {
        __syncthreads();
        #pragma unroll
        for (int it = 0; it < 8; it++) {
            int c = kc + it*4 + cl;
            float4 v = *(const float4*)(xp + (size_t)c*HWSZ + p4);
            *(float4*)&xs[it*4 + cl][p4] = v;
        }
        __syncthreads();

        #pragma unroll
        for (int c = 0; c < 32; c++) {
            float4 xv = *(float4*)&xs[c][tp*4];
            float4 wa = *(float4*)&ws[kc + c][tk*8];
            float4 wb = *(float4*)&ws[kc + c][tk*8 + 4];
            float xr[4] = {xv.x, xv.y, xv.z, xv.w};
            float wr[8] = {wa.x, wa.y, wa.z, wa.w, wb.x, wb.y, wb.z, wb.w};
            #pragma unroll
            for (int p = 0; p < 4; p++)
                #pragma unroll
                for (int q = 0; q < 8; q++)
                    acc[p][q] += xr[p] * wr[q];
        }
    }

    // ---- epilogue: bias, then inclusive row scan per channel ----
    const int lane = tid & 31;
    const int wid  = tid >> 5;
    float tot[8];

    #pragma unroll
    for (int q = 0; q < 8; q++) {
        int k = tk*8 + q;
        float inv  = g1[k] * rsqrtf(v1[k] + 1e-5f);
        float bias = b1[k] - m1[k]*inv;
        float a0 = acc[0][q] + bias;
        float a1 = acc[1][q] + bias;
        float a2 = acc[2][q] + bias;
        float a3 = acc[3][q] + bias;
        acc[0][q] = a0;
        acc[1][q] = a0 + a1;
        acc[2][q] = acc[1][q] + a2;
        acc[3][q] = acc[2][q] + a3;
        float s = acc[3][q];
        #pragma unroll
        for (int o = 1; o < 32; o <<= 1) {
            float t = __shfl_up_sync(0xffffffffu, s, o);
            if (lane >= o) s += t;
        }
        tot[q] = s;
        if (lane == 31) wtot[wid][q] = s;
    }
    __syncthreads();

    #pragma unroll
    for (int q = 0; q < 8; q++) {
        int k = tk*8 + q;
        float off = tot[q] - acc[3][q];
        if (wid & 1) off += wtot[wid - 1][q];
        float4 r = make_float4(acc[0][q] + off, acc[1][q] + off,
                               acc[2][q] + off, acc[3][q] + off);
        *(float4*)(g_z + (size_t)(b*BTC + k)*HWSZ + ij + tp*4) = r;
    }
}

// ---------------------------------------------------------------------------
// Kernel 2a: chunk-local column cumsum of row-scanned z into S (+ zero borders)
// grid = (chunk 0..3, plane 0..127); each block does 64 rows, saves chunk totals.
// ---------------------------------------------------------------------------
__global__ __launch_bounds__(256) void k2a_colsum_chunk()
{
    const int chunk = blockIdx.x;            // 0..3
    const int plane = blockIdx.y;            // 0..127
    const int j     = threadIdx.x;
    const int r0    = chunk * 64;

    const float* zp = g_z + (size_t)plane*HWSZ + (size_t)r0*WW + j;
    float* Sp = g_S + (size_t)plane*SW*SW;

    // borders
    if (chunk == 0) {
        Sp[j] = 0.f;                         // top row, cols 0..255
        if (j == 0) Sp[256] = 0.f;           // top row, col 256
    }
    if (j < 64)                              // left column for this chunk's rows
        Sp[(size_t)(r0 + j + 1)*SW] = 0.f;

    float acc = 0.f;
    #pragma unroll 8
    for (int r = 0; r < 64; r++) {
        acc += zp[(size_t)r*WW];
        Sp[(size_t)(r0 + r + 1)*SW + (j + 1)] = acc;
    }
    g_ctot[plane][chunk][j] = acc;
}

// ---------------------------------------------------------------------------
// Kernel 2b: add prefix of earlier chunk totals to chunks 1..3 of S.
// grid = (chunk-1 0..2, plane); fully parallel rows -> high MLP.
// ---------------------------------------------------------------------------
__global__ __launch_bounds__(256) void k2b_fixup()
{
    const int chunk = blockIdx.x + 1;        // 1..3
    const int plane = blockIdx.y;
    const int j     = threadIdx.x;
    const int r0    = chunk * 64;

    float off = g_ctot[plane][0][j];
    for (int p = 1; p < chunk; p++)
        off += g_ctot[plane][p][j];

    float* Sp = g_S + (size_t)plane*SW*SW + (size_t)(r0 + 1)*SW + (j + 1);
    #pragma unroll 8
    for (int r = 0; r < 64; r++)
        Sp[(size_t)r*SW] += off;
}

// ---------------------------------------------------------------------------
// Kernel 3: separable box filter via shared vertical-difference vector.
// (round-3 version — known-good 95.6us @ occ 94%)
// ---------------------------------------------------------------------------
__global__ __launch_bounds__(256) void k3_box(
    const float* __restrict__ x,
    const float* __restrict__ xmn_, const float* __restrict__ xmx_,
    const float* __restrict__ ymn_, const float* __restrict__ ymx_,
    const float* __restrict__ g2, const float* __restrict__ b2,
    const float* __restrict__ m2, const float* __restrict__ v2,
    float* __restrict__ out)
{
    __shared__ float Dv[8][SW];

    const int bid = blockIdx.x;
    const int rc  = bid & 31;
    const int nb  = (bid >> 5) & (NBOX-1);
    const int bt  = (bid >> 7) & (BTC-1);
    const int b   = bid >> 12;
    const int j   = threadIdx.x;
    const int k   = bt*NBOX + nb;
    const int boxi = bt*NBOX + nb;

    const float xmn = xmn_[boxi], xmx = xmx_[boxi];
    const float ymn = ymn_[boxi], ymx = ymx_[boxi];
    const float inv_area = 1.f / ((xmx - xmn) * (ymx - ymn));

    const float* Sp = g_S + (size_t)(b*BTC + bt)*SW*SW;

    #pragma unroll
    for (int r = 0; r < 8; r++) {
        int i = rc*8 + r;
        float uA = fminf(fmaxf((float)i + xmx, 0.f), 256.f);
        float uB = fminf(fmaxf((float)i + xmn, 0.f), 256.f);
        float fA = fminf(floorf(uA), 255.f);
        float fB = fminf(floorf(uB), 255.f);
        int   iA = (int)fA, iB = (int)fB;
        float wA = uA - fA, wB = uB - fB;

        const float* RA0 = Sp + (size_t)iA*SW;
        const float* RB0 = Sp + (size_t)iB*SW;

        float d = (RA0[j]*(1.f-wA) + RA0[SW+j]*wA)
                - (RB0[j]*(1.f-wB) + RB0[SW+j]*wB);
        Dv[r][j] = d;
        if (j == 255) {
            float d2 = (RA0[256]*(1.f-wA) + RA0[SW+256]*wA)
                     - (RB0[256]*(1.f-wB) + RB0[SW+256]*wB);
            Dv[r][256] = d2;
        }
    }
    __syncthreads();

    float vA = fminf(fmaxf((float)j + ymx, 0.f), 256.f);
    float vB = fminf(fmaxf((float)j + ymn, 0.f), 256.f);
    float gA = fminf(floorf(vA), 255.f);
    float gB = fminf(floorf(vB), 255.f);
    int   jA = (int)gA, jB = (int)gB;
    float wvA = vA - gA, wvB = vB - gB;

    float inv2  = g2[k] * rsqrtf(v2[k] + 1e-3f);
    float bias2 = b2[k] - m2[k]*inv2;

    const float* xrow = x   + ((size_t)(b*CC + k)*HH + rc*8)*WW + j;
    float*       orow = out + ((size_t)(b*CC + k)*HH + rc*8)*WW + j;

    #pragma unroll
    for (int r = 0; r < 8; r++) {
        float DA = Dv[r][jA]*(1.f - wvA) + Dv[r][jA+1]*wvA;
        float DB = Dv[r][jB]*(1.f - wvB) + Dv[r][jB+1]*wvB;
        float val = (DA - DB) * inv_area;

        val = fmaxf(val*inv2 + bias2, 0.f);
        orow[(size_t)r*WW] = fmaxf(xrow[(size_t)r*WW] + val, 0.f);
    }
}

// ---------------------------------------------------------------------------
extern "C" void kernel_launch(void* const* d_in, const int* in_sizes, int n_in,
                              void* d_out, int out_size)
{
    const float* x    = (const float*)d_in[0];
    const float* w1   = (const float*)d_in[1];
    const float* g1   = (const float*)d_in[2];
    const float* b1   = (const float*)d_in[3];
    const float* m1   = (const float*)d_in[4];
    const float* v1   = (const float*)d_in[5];
    const float* xmn  = (const float*)d_in[6];
    const float* xmx  = (const float*)d_in[7];
    const float* ymn  = (const float*)d_in[8];
    const float* ymx  = (const float*)d_in[9];
    const float* g2   = (const float*)d_in[10];
    const float* b2   = (const float*)d_in[11];
    const float* m2   = (const float*)d_in[12];
    const float* v2   = (const float*)d_in[13];
    float* out = (float*)d_out;

    k1_conv_bn_rowscan<<<(BB*HWSZ)/256, 256>>>(x, w1, g1, b1, m1, v1);
    k2a_colsum_chunk<<<dim3(4, BB*BTC), 256>>>();
    k2b_fixup<<<dim3(3, BB*BTC), 256>>>();
    k3_box<<<BB*BTC*NBOX*(HH/8), 256>>>(x, xmn, xmx, ymn, ymx, g2, b2, m2, v2, out);
}

// round 7
// speedup vs baseline: 1.4979x; 1.1439x over previous
#include <cuda_runtime.h>
#include <math.h>

#define BB 4
#define CC 128
#define NBOX 4
#define BTC 32
#define HH 256
#define WW 256
#define HWSZ (HH*WW)
#define SW 257                      // integral image row stride

// scratch (static device globals; no dynamic allocation)
__device__ float g_z[BB*BTC*HH*WW];       // ROW-SCANNED z = rowcumsum(BN1(conv))
__device__ float g_S[BB*BTC*SW*SW];       // 2D integral image, zero borders
__device__ float g_ctot[BB*BTC][4][WW];   // per-chunk column totals

// ---------------------------------------------------------------------------
// Kernel 1: z = rowcumsum( BN1(x @ w1^T) )
// block = one image row (b, i): 256 px x 32 channels.
// ---------------------------------------------------------------------------
__global__ __launch_bounds__(256) void k1_conv_bn_rowscan(
    const float* __restrict__ x, const float* __restrict__ w1,
    const float* __restrict__ g1, const float* __restrict__ b1,
    const float* __restrict__ m1, const float* __restrict__ v1)
{
    __shared__ float xs[32][256];
    __shared__ float ws[128][32];
    __shared__ float wtot[8][8];

    const int tid = threadIdx.x;

    for (int idx = tid; idx < CC*BTC; idx += 256) {
        int k = idx & 31;
        int c = idx >> 5;
        float inv = g1[k] * rsqrtf(v1[k] + 1e-5f);
        ws[c][k] = w1[k*CC + c] * inv;
    }

    const int pixbase = blockIdx.x * 256;
    const int b  = pixbase >> 16;
    const int ij = pixbase & 65535;
    const float* xp = x + (size_t)b*CC*HWSZ + ij;

    const int tp = tid & 63;
    const int tk = tid >> 6;

    float acc[4][8];
    #pragma unroll
    for (int p = 0; p < 4; p++)
        #pragma unroll
        for (int q = 0; q < 8; q++) acc[p][q] = 0.f;

    const int cl = tid >> 6;
    const int p4 = (tid & 63) * 4;

    for (int kc = 0; kc < CC; kc += 32) {
        __syncthreads();
        #pragma unroll
        for (int it = 0; it < 8; it++) {
            int c = kc + it*4 + cl;
            float4 v = *(const float4*)(xp + (size_t)c*HWSZ + p4);
            *(float4*)&xs[it*4 + cl][p4] = v;
        }
        __syncthreads();

        #pragma unroll
        for (int c = 0; c < 32; c++) {
            float4 xv = *(float4*)&xs[c][tp*4];
            float4 wa = *(float4*)&ws[kc + c][tk*8];
            float4 wb = *(float4*)&ws[kc + c][tk*8 + 4];
            float xr[4] = {xv.x, xv.y, xv.z, xv.w};
            float wr[8] = {wa.x, wa.y, wa.z, wa.w, wb.x, wb.y, wb.z, wb.w};
            #pragma unroll
            for (int p = 0; p < 4; p++)
                #pragma unroll
                for (int q = 0; q < 8; q++)
                    acc[p][q] += xr[p] * wr[q];
        }
    }

    // ---- epilogue: bias, then inclusive row scan per channel ----
    const int lane = tid & 31;
    const int wid  = tid >> 5;
    float tot[8];

    #pragma unroll
    for (int q = 0; q < 8; q++) {
        int k = tk*8 + q;
        float inv  = g1[k] * rsqrtf(v1[k] + 1e-5f);
        float bias = b1[k] - m1[k]*inv;
        float a0 = acc[0][q] + bias;
        float a1 = acc[1][q] + bias;
        float a2 = acc[2][q] + bias;
        float a3 = acc[3][q] + bias;
        acc[0][q] = a0;
        acc[1][q] = a0 + a1;
        acc[2][q] = acc[1][q] + a2;
        acc[3][q] = acc[2][q] + a3;
        float s = acc[3][q];
        #pragma unroll
        for (int o = 1; o < 32; o <<= 1) {
            float t = __shfl_up_sync(0xffffffffu, s, o);
            if (lane >= o) s += t;
        }
        tot[q] = s;
        if (lane == 31) wtot[wid][q] = s;
    }
    __syncthreads();

    #pragma unroll
    for (int q = 0; q < 8; q++) {
        int k = tk*8 + q;
        float off = tot[q] - acc[3][q];
        if (wid & 1) off += wtot[wid - 1][q];
        float4 r = make_float4(acc[0][q] + off, acc[1][q] + off,
                               acc[2][q] + off, acc[3][q] + off);
        *(float4*)(g_z + (size_t)(b*BTC + k)*HWSZ + ij + tp*4) = r;
    }
}

// ---------------------------------------------------------------------------
// Kernel 2pre: per-chunk column totals of row-scanned z.
// grid = (chunk 0..3, plane 0..127); writes g_ctot only (no S traffic).
// ---------------------------------------------------------------------------
__global__ __launch_bounds__(256) void k2pre_chunktot()
{
    const int chunk = blockIdx.x;
    const int plane = blockIdx.y;
    const int j     = threadIdx.x;
    const float* zp = g_z + (size_t)plane*HWSZ + (size_t)(chunk*64)*WW + j;

    float acc = 0.f;
    #pragma unroll 8
    for (int r = 0; r < 64; r++)
        acc += zp[(size_t)r*WW];
    g_ctot[plane][chunk][j] = acc;
}

// ---------------------------------------------------------------------------
// Kernel 2a: chunk column cumsum seeded with earlier-chunk prefix -> FINAL S.
// grid = (chunk 0..3, plane 0..127). No RMW pass needed.
// ---------------------------------------------------------------------------
__global__ __launch_bounds__(256) void k2a_colsum_chunk()
{
    const int chunk = blockIdx.x;            // 0..3
    const int plane = blockIdx.y;            // 0..127
    const int j     = threadIdx.x;
    const int r0    = chunk * 64;

    const float* zp = g_z + (size_t)plane*HWSZ + (size_t)r0*WW + j;
    float* Sp = g_S + (size_t)plane*SW*SW;

    // borders
    if (chunk == 0) {
        Sp[j] = 0.f;                         // top row, cols 0..255
        if (j == 0) Sp[256] = 0.f;           // top row, col 256
    }
    if (j < 64)                              // left column for this chunk's rows
        Sp[(size_t)(r0 + j + 1)*SW] = 0.f;

    // seed with prefix of earlier chunk totals (L2-resident, tiny)
    float acc = 0.f;
    for (int p = 0; p < chunk; p++)
        acc += g_ctot[plane][p][j];

    #pragma unroll 8
    for (int r = 0; r < 64; r++) {
        acc += zp[(size_t)r*WW];
        Sp[(size_t)(r0 + r + 1)*SW + (j + 1)] = acc;
    }
}

// ---------------------------------------------------------------------------
// Kernel 3: separable box filter via shared vertical-difference vector.
// (known-good ~95us @ occ 94%)
// ---------------------------------------------------------------------------
__global__ __launch_bounds__(256) void k3_box(
    const float* __restrict__ x,
    const float* __restrict__ xmn_, const float* __restrict__ xmx_,
    const float* __restrict__ ymn_, const float* __restrict__ ymx_,
    const float* __restrict__ g2, const float* __restrict__ b2,
    const float* __restrict__ m2, const float* __restrict__ v2,
    float* __restrict__ out)
{
    __shared__ float Dv[8][SW];

    const int bid = blockIdx.x;
    const int rc  = bid & 31;
    const int nb  = (bid >> 5) & (NBOX-1);
    const int bt  = (bid >> 7) & (BTC-1);
    const int b   = bid >> 12;
    const int j   = threadIdx.x;
    const int k   = bt*NBOX + nb;
    const int boxi = bt*NBOX + nb;

    const float xmn = xmn_[boxi], xmx = xmx_[boxi];
    const float ymn = ymn_[boxi], ymx = ymx_[boxi];
    const float inv_area = 1.f / ((xmx - xmn) * (ymx - ymn));

    const float* Sp = g_S + (size_t)(b*BTC + bt)*SW*SW;

    #pragma unroll
    for (int r = 0; r < 8; r++) {
        int i = rc*8 + r;
        float uA = fminf(fmaxf((float)i + xmx, 0.f), 256.f);
        float uB = fminf(fmaxf((float)i + xmn, 0.f), 256.f);
        float fA = fminf(floorf(uA), 255.f);
        float fB = fminf(floorf(uB), 255.f);
        int   iA = (int)fA, iB = (int)fB;
        float wA = uA - fA, wB = uB - fB;

        const float* RA0 = Sp + (size_t)iA*SW;
        const float* RB0 = Sp + (size_t)iB*SW;

        float d = (RA0[j]*(1.f-wA) + RA0[SW+j]*wA)
                - (RB0[j]*(1.f-wB) + RB0[SW+j]*wB);
        Dv[r][j] = d;
        if (j == 255) {
            float d2 = (RA0[256]*(1.f-wA) + RA0[SW+256]*wA)
                     - (RB0[256]*(1.f-wB) + RB0[SW+256]*wB);
            Dv[r][256] = d2;
        }
    }
    __syncthreads();

    float vA = fminf(fmaxf((float)j + ymx, 0.f), 256.f);
    float vB = fminf(fmaxf((float)j + ymn, 0.f), 256.f);
    float gA = fminf(floorf(vA), 255.f);
    float gB = fminf(floorf(vB), 255.f);
    int   jA = (int)gA, jB = (int)gB;
    float wvA = vA - gA, wvB = vB - gB;

    float inv2  = g2[k] * rsqrtf(v2[k] + 1e-3f);
    float bias2 = b2[k] - m2[k]*inv2;

    const float* xrow = x   + ((size_t)(b*CC + k)*HH + rc*8)*WW + j;
    float*       orow = out + ((size_t)(b*CC + k)*HH + rc*8)*WW + j;

    #pragma unroll
    for (int r = 0; r < 8; r++) {
        float DA = Dv[r][jA]*(1.f - wvA) + Dv[r][jA+1]*wvA;
        float DB = Dv[r][jB]*(1.f - wvB) + Dv[r][jB+1]*wvB;
        float val = (DA - DB) * inv_area;

        val = fmaxf(val*inv2 + bias2, 0.f);
        orow[(size_t)r*WW] = fmaxf(xrow[(size_t)r*WW] + val, 0.f);
    }
}

// ---------------------------------------------------------------------------
extern "C" void kernel_launch(void* const* d_in, const int* in_sizes, int n_in,
                              void* d_out, int out_size)
{
    const float* x    = (const float*)d_in[0];
    const float* w1   = (const float*)d_in[1];
    const float* g1   = (const float*)d_in[2];
    const float* b1   = (const float*)d_in[3];
    const float* m1   = (const float*)d_in[4];
    const float* v1   = (const float*)d_in[5];
    const float* xmn  = (const float*)d_in[6];
    const float* xmx  = (const float*)d_in[7];
    const float* ymn  = (const float*)d_in[8];
    const float* ymx  = (const float*)d_in[9];
    const float* g2   = (const float*)d_in[10];
    const float* b2   = (const float*)d_in[11];
    const float* m2   = (const float*)d_in[12];
    const float* v2   = (const float*)d_in[13];
    float* out = (float*)d_out;

    k1_conv_bn_rowscan<<<(BB*HWSZ)/256, 256>>>(x, w1, g1, b1, m1, v1);
    k2pre_chunktot<<<dim3(4, BB*BTC), 256>>>();
    k2a_colsum_chunk<<<dim3(4, BB*BTC), 256>>>();
    k3_box<<<BB*BTC*NBOX*(HH/8), 256>>>(x, xmn, xmx, ymn, ymx, g2, b2, m2, v2, out);
}

// round 8
// speedup vs baseline: 1.6755x; 1.1186x over previous
#include <cuda_runtime.h>
#include <math.h>

#define BB 4
#define CC 128
#define NBOX 4
#define BTC 32
#define HH 256
#define WW 256
#define HWSZ (HH*WW)
#define SW 257                      // integral image row stride

// scratch (static device globals; no dynamic allocation)
__device__ float g_z[BB*BTC*HH*WW];       // ROW-SCANNED z = rowcumsum(BN1(conv))
__device__ float g_S[BB*BTC*SW*SW];       // 2D integral image, zero borders
__device__ float g_ctot[BB*BTC][4][WW];   // per-chunk column totals

// ---------------------------------------------------------------------------
// Kernel 1: z = rowcumsum( BN1(x @ w1^T) )
// block = one image row (b, i): 256 px x 32 channels.
// ---------------------------------------------------------------------------
__global__ __launch_bounds__(256) void k1_conv_bn_rowscan(
    const float* __restrict__ x, const float* __restrict__ w1,
    const float* __restrict__ g1, const float* __restrict__ b1,
    const float* __restrict__ m1, const float* __restrict__ v1)
{
    __shared__ float xs[32][256];
    __shared__ float ws[128][32];
    __shared__ float wtot[8][8];

    const int tid = threadIdx.x;

    for (int idx = tid; idx < CC*BTC; idx += 256) {
        int k = idx & 31;
        int c = idx >> 5;
        float inv = g1[k] * rsqrtf(v1[k] + 1e-5f);
        ws[c][k] = w1[k*CC + c] * inv;
    }

    const int pixbase = blockIdx.x * 256;
    const int b  = pixbase >> 16;
    const int ij = pixbase & 65535;
    const float* xp = x + (size_t)b*CC*HWSZ + ij;

    const int tp = tid & 63;
    const int tk = tid >> 6;

    float acc[4][8];
    #pragma unroll
    for (int p = 0; p < 4; p++)
        #pragma unroll
        for (int q = 0; q < 8; q++) acc[p][q] = 0.f;

    const int cl = tid >> 6;
    const int p4 = (tid & 63) * 4;

    for (int kc = 0; kc < CC; kc += 32) {
        __syncthreads();
        #pragma unroll
        for (int it = 0; it < 8; it++) {
            int c = kc + it*4 + cl;
            float4 v = *(const float4*)(xp + (size_t)c*HWSZ + p4);
            *(float4*)&xs[it*4 + cl][p4] = v;
        }
        __syncthreads();

        #pragma unroll
        for (int c = 0; c < 32; c++) {
            float4 xv = *(float4*)&xs[c][tp*4];
            float4 wa = *(float4*)&ws[kc + c][tk*8];
            float4 wb = *(float4*)&ws[kc + c][tk*8 + 4];
            float xr[4] = {xv.x, xv.y, xv.z, xv.w};
            float wr[8] = {wa.x, wa.y, wa.z, wa.w, wb.x, wb.y, wb.z, wb.w};
            #pragma unroll
            for (int p = 0; p < 4; p++)
                #pragma unroll
                for (int q = 0; q < 8; q++)
                    acc[p][q] += xr[p] * wr[q];
        }
    }

    // ---- epilogue: bias, then inclusive row scan per channel ----
    const int lane = tid & 31;
    const int wid  = tid >> 5;
    float tot[8];

    #pragma unroll
    for (int q = 0; q < 8; q++) {
        int k = tk*8 + q;
        float inv  = g1[k] * rsqrtf(v1[k] + 1e-5f);
        float bias = b1[k] - m1[k]*inv;
        float a0 = acc[0][q] + bias;
        float a1 = acc[1][q] + bias;
        float a2 = acc[2][q] + bias;
        float a3 = acc[3][q] + bias;
        acc[0][q] = a0;
        acc[1][q] = a0 + a1;
        acc[2][q] = acc[1][q] + a2;
        acc[3][q] = acc[2][q] + a3;
        float s = acc[3][q];
        #pragma unroll
        for (int o = 1; o < 32; o <<= 1) {
            float t = __shfl_up_sync(0xffffffffu, s, o);
            if (lane >= o) s += t;
        }
        tot[q] = s;
        if (lane == 31) wtot[wid][q] = s;
    }
    __syncthreads();

    #pragma unroll
    for (int q = 0; q < 8; q++) {
        int k = tk*8 + q;
        float off = tot[q] - acc[3][q];
        if (wid & 1) off += wtot[wid - 1][q];
        float4 r = make_float4(acc[0][q] + off, acc[1][q] + off,
                               acc[2][q] + off, acc[3][q] + off);
        *(float4*)(g_z + (size_t)(b*BTC + k)*HWSZ + ij + tp*4) = r;
    }
}

// ---------------------------------------------------------------------------
// Kernel 2pre: per-chunk column totals of row-scanned z.
// ---------------------------------------------------------------------------
__global__ __launch_bounds__(256) void k2pre_chunktot()
{
    const int chunk = blockIdx.x;
    const int plane = blockIdx.y;
    const int j     = threadIdx.x;
    const float* zp = g_z + (size_t)plane*HWSZ + (size_t)(chunk*64)*WW + j;

    float acc = 0.f;
    #pragma unroll 8
    for (int r = 0; r < 64; r++)
        acc += zp[(size_t)r*WW];
    g_ctot[plane][chunk][j] = acc;
}

// ---------------------------------------------------------------------------
// Kernel 2a: chunk column cumsum seeded with earlier-chunk prefix -> FINAL S.
// ---------------------------------------------------------------------------
__global__ __launch_bounds__(256) void k2a_colsum_chunk()
{
    const int chunk = blockIdx.x;            // 0..3
    const int plane = blockIdx.y;            // 0..127
    const int j     = threadIdx.x;
    const int r0    = chunk * 64;

    const float* zp = g_z + (size_t)plane*HWSZ + (size_t)r0*WW + j;
    float* Sp = g_S + (size_t)plane*SW*SW;

    if (chunk == 0) {
        Sp[j] = 0.f;
        if (j == 0) Sp[256] = 0.f;
    }
    if (j < 64)
        Sp[(size_t)(r0 + j + 1)*SW] = 0.f;

    float acc = 0.f;
    for (int p = 0; p < chunk; p++)
        acc += g_ctot[plane][p][j];

    #pragma unroll 8
    for (int r = 0; r < 64; r++) {
        acc += zp[(size_t)r*WW];
        Sp[(size_t)(r0 + r + 1)*SW + (j + 1)] = acc;
    }
}

// ---------------------------------------------------------------------------
// Kernel 3: separable box filter, row-march phase 1.
// Within a block the vertical weights wA,wB are row-invariant and tap rows
// march by +1, so 8 rows need only 9+9 S loads per thread (split in halves
// to cap registers). Clamps handled exactly: row<0 -> 0, row>256 -> S[256].
// ---------------------------------------------------------------------------
__global__ __launch_bounds__(256) void k3_box(
    const float* __restrict__ x,
    const float* __restrict__ xmn_, const float* __restrict__ xmx_,
    const float* __restrict__ ymn_, const float* __restrict__ ymx_,
    const float* __restrict__ g2, const float* __restrict__ b2,
    const float* __restrict__ m2, const float* __restrict__ v2,
    float* __restrict__ out)
{
    __shared__ float Dv[8][SW];

    const int bid = blockIdx.x;
    const int rc  = bid & 31;
    const int nb  = (bid >> 5) & (NBOX-1);
    const int bt  = (bid >> 7) & (BTC-1);
    const int b   = bid >> 12;
    const int j   = threadIdx.x;
    const int k   = bt*NBOX + nb;
    const int boxi = bt*NBOX + nb;

    const float xmn = xmn_[boxi], xmx = xmx_[boxi];
    const float ymn = ymn_[boxi], ymx = ymx_[boxi];
    const float inv_area = 1.f / ((xmx - xmn) * (ymx - ymn));

    const float* Sp = g_S + (size_t)(b*BTC + bt)*SW*SW;

    // ---- phase 1: row-march vertical lerp-difference ----
    const int i0 = rc*8;
    const float aA = (float)i0 + xmx;          // raw (unclamped) anchors
    const float aB = (float)i0 + xmn;
    const float fAf = floorf(aA), fBf = floorf(aB);
    const int   rA0 = (int)fAf,  rB0 = (int)fBf;
    const float wA = aA - fAf,   wB = aB - fBf;

    #pragma unroll
    for (int half = 0; half < 2; half++) {
        int rh = half*4;
        float SA[5], SB[5];
        #pragma unroll
        for (int t = 0; t < 5; t++) {
            int ra = rA0 + rh + t;  ra = (ra > 256) ? 256 : ra;
            int rb = rB0 + rh + t;  rb = (rb > 256) ? 256 : rb;
            SA[t] = (ra < 0) ? 0.f : Sp[(size_t)ra*SW + j];
            SB[t] = (rb < 0) ? 0.f : Sp[(size_t)rb*SW + j];
        }
        #pragma unroll
        for (int t = 0; t < 4; t++)
            Dv[rh + t][j] = (SA[t]*(1.f-wA) + SA[t+1]*wA)
                          - (SB[t]*(1.f-wB) + SB[t+1]*wB);
        if (j == 255) {   // column 256
            float TA[5], TB[5];
            #pragma unroll
            for (int t = 0; t < 5; t++) {
                int ra = rA0 + rh + t;  ra = (ra > 256) ? 256 : ra;
                int rb = rB0 + rh + t;  rb = (rb > 256) ? 256 : rb;
                TA[t] = (ra < 0) ? 0.f : Sp[(size_t)ra*SW + 256];
                TB[t] = (rb < 0) ? 0.f : Sp[(size_t)rb*SW + 256];
            }
            #pragma unroll
            for (int t = 0; t < 4; t++)
                Dv[rh + t][256] = (TA[t]*(1.f-wA) + TA[t+1]*wA)
                                - (TB[t]*(1.f-wB) + TB[t+1]*wB);
        }
    }
    __syncthreads();

    // ---- phase 2: horizontal fractional box from smem ----
    float vA = fminf(fmaxf((float)j + ymx, 0.f), 256.f);
    float vB = fminf(fmaxf((float)j + ymn, 0.f), 256.f);
    float gA = fminf(floorf(vA), 255.f);
    float gB = fminf(floorf(vB), 255.f);
    int   jA = (int)gA, jB = (int)gB;
    float wvA = vA - gA, wvB = vB - gB;

    float inv2  = g2[k] * rsqrtf(v2[k] + 1e-3f);
    float bias2 = b2[k] - m2[k]*inv2;

    const float* xrow = x   + ((size_t)(b*CC + k)*HH + i0)*WW + j;
    float*       orow = out + ((size_t)(b*CC + k)*HH + i0)*WW + j;

    #pragma unroll
    for (int r = 0; r < 8; r++) {
        float DA = Dv[r][jA]*(1.f - wvA) + Dv[r][jA+1]*wvA;
        float DB = Dv[r][jB]*(1.f - wvB) + Dv[r][jB+1]*wvB;
        float val = (DA - DB) * inv_area;

        val = fmaxf(val*inv2 + bias2, 0.f);
        orow[(size_t)r*WW] = fmaxf(xrow[(size_t)r*WW] + val, 0.f);
    }
}

// ---------------------------------------------------------------------------
extern "C" void kernel_launch(void* const* d_in, const int* in_sizes, int n_in,
                              void* d_out, int out_size)
{
    const float* x    = (const float*)d_in[0];
    const float* w1   = (const float*)d_in[1];
    const float* g1   = (const float*)d_in[2];
    const float* b1   = (const float*)d_in[3];
    const float* m1   = (const float*)d_in[4];
    const float* v1   = (const float*)d_in[5];
    const float* xmn  = (const float*)d_in[6];
    const float* xmx  = (const float*)d_in[7];
    const float* ymn  = (const float*)d_in[8];
    const float* ymx  = (const float*)d_in[9];
    const float* g2   = (const float*)d_in[10];
    const float* b2   = (const float*)d_in[11];
    const float* m2   = (const float*)d_in[12];
    const float* v2   = (const float*)d_in[13];
    float* out = (float*)d_out;

    k1_conv_bn_rowscan<<<(BB*HWSZ)/256, 256>>>(x, w1, g1, b1, m1, v1);
    k2pre_chunktot<<<dim3(4, BB*BTC), 256>>>();
    k2a_colsum_chunk<<<dim3(4, BB*BTC), 256>>>();
    k3_box<<<BB*BTC*NBOX*(HH/8), 256>>>(x, xmn, xmx, ymn, ymx, g2, b2, m2, v2, out);
}

// round 10
// speedup vs baseline: 1.8338x; 1.0944x over previous
#include <cuda_runtime.h>
#include <math.h>
#include <stdint.h>

#define BB 4
#define CC 128
#define NBOX 4
#define BTC 32
#define HH 256
#define WW 256
#define HWSZ (HH*WW)
#define SW 257                      // integral image row stride

// scratch (static device globals; no dynamic allocation)
__device__ float g_z[BB*BTC*HH*WW];       // ROW-SCANNED z = rowcumsum(BN1(conv))
__device__ float g_S[BB*BTC*SW*SW];       // 2D integral image, zero borders
__device__ float g_ctot[BB*BTC][4][WW];   // per-chunk column totals

__device__ __forceinline__ uint32_t f2tf32(float f) {
    uint32_t r;
    asm("cvt.rna.tf32.f32 %0, %1;" : "=r"(r) : "f"(f));
    return r;
}
__device__ __forceinline__ void mma_tf32(float d[4], const uint32_t a[4],
                                         const uint32_t b[2]) {
    asm volatile(
        "mma.sync.aligned.m16n8k8.row.col.f32.tf32.tf32.f32 "
        "{%0,%1,%2,%3}, {%4,%5,%6,%7}, {%8,%9}, {%0,%1,%2,%3};\n"
        : "+f"(d[0]), "+f"(d[1]), "+f"(d[2]), "+f"(d[3])
        : "r"(a[0]), "r"(a[1]), "r"(a[2]), "r"(a[3]), "r"(b[0]), "r"(b[1]));
}

// dynamic smem layout for k1 (bytes)
#define SM_SINV  0        // 32 f
#define SM_SBIAS 128      // 32 f
#define SM_WTOT  256      // [8][8] f
#define SM_WS    512      // [128][36] u32 tf32 weights  (18432 B)
#define SM_ZS    18944    // [32][260] f                 (33280 B)
#define SM_TOTAL 52224

// ---------------------------------------------------------------------------
// Kernel 1: z = rowcumsum( BN1(x @ w1^T) )  via mma.sync tf32 (HMMA).
// block = one image row (256 px); warp w -> px [w*32, w*32+32) x 32 channels.
// A fragments straight from global x (sector-exact), B tf32 in smem.
// Epilogue: acc -> zs smem -> bias + per-channel row scan -> g_z.
// ---------------------------------------------------------------------------
__global__ __launch_bounds__(256) void k1_mma_rowscan(
    const float* __restrict__ x, const float* __restrict__ w1,
    const float* __restrict__ g1, const float* __restrict__ b1,
    const float* __restrict__ m1, const float* __restrict__ v1)
{
    extern __shared__ char dsm[];
    float*    sinv  = (float*)(dsm + SM_SINV);
    float*    sbias = (float*)(dsm + SM_SBIAS);
    float*    wtot  = (float*)(dsm + SM_WTOT);
    uint32_t* wst   = (uint32_t*)(dsm + SM_WS);
    float*    zs    = (float*)(dsm + SM_ZS);

    const int tid  = threadIdx.x;
    const int w    = tid >> 5;
    const int lane = tid & 31;
    const int g    = lane >> 2;     // group id 0..7
    const int t    = lane & 3;      // thread-in-group 0..3

    const int pixbase = blockIdx.x * 256;
    const int b  = pixbase >> 16;
    const int ij = pixbase & 65535;

    if (tid < 32) {
        float inv = g1[tid] * rsqrtf(v1[tid] + 1e-5f);
        sinv[tid]  = inv;
        sbias[tid] = b1[tid] - m1[tid]*inv;
    }
    __syncthreads();

    // stage B = w1 * inv (tf32), layout wst[c][ch], pad 36
    for (int idx = tid; idx < CC*BTC; idx += 256) {
        int c  = idx >> 5;
        int ch = idx & 31;
        wst[c*36 + ch] = f2tf32(w1[ch*CC + c] * sinv[ch]);
    }
    __syncthreads();

    float acc[2][4][4];
    #pragma unroll
    for (int mt = 0; mt < 2; mt++)
        #pragma unroll
        for (int nt = 0; nt < 4; nt++)
            #pragma unroll
            for (int e = 0; e < 4; e++) acc[mt][nt][e] = 0.f;

    const float* xb = x + (size_t)b*CC*HWSZ + ij + w*32 + g;

    #pragma unroll
    for (int ks = 0; ks < 16; ks++) {
        const int k0 = ks * 8;
        uint32_t a[2][4];
        #pragma unroll
        for (int mt = 0; mt < 2; mt++) {
            const float* xp = xb + mt*16;
            const size_t co = (size_t)(k0 + t)*HWSZ;
            a[mt][0] = f2tf32(xp[co]);
            a[mt][1] = f2tf32(xp[co + 8]);
            a[mt][2] = f2tf32(xp[co + 4*(size_t)HWSZ]);
            a[mt][3] = f2tf32(xp[co + 4*(size_t)HWSZ + 8]);
        }
        #pragma unroll
        for (int nt = 0; nt < 4; nt++) {
            uint32_t bf[2];
            bf[0] = wst[(k0 + t)*36 + nt*8 + g];
            bf[1] = wst[(k0 + t + 4)*36 + nt*8 + g];
            mma_tf32(acc[0][nt], a[0], bf);
            mma_tf32(acc[1][nt], a[1], bf);
        }
    }

    // ---- scatter acc to zs[ch][260] (conflict-free, float4-aligned rows) ----
    #pragma unroll
    for (int mt = 0; mt < 2; mt++) {
        const int px = w*32 + mt*16 + g;
        #pragma unroll
        for (int nt = 0; nt < 4; nt++) {
            const int ch = nt*8 + 2*t;
            zs[ch*260 + px]           = acc[mt][nt][0];
            zs[(ch+1)*260 + px]       = acc[mt][nt][1];
            zs[ch*260 + px + 8]       = acc[mt][nt][2];
            zs[(ch+1)*260 + px + 8]   = acc[mt][nt][3];
        }
    }
    __syncthreads();

    // ---- bias + per-channel inclusive row scan (round-5 proven pattern) ----
    const int tp  = tid & 63;       // pixel group (4 px)
    const int tk  = tid >> 6;       // channel group (8 ch)
    const int wid = tid >> 5;

    float sc[4][8];
    float tot[8];
    #pragma unroll
    for (int q = 0; q < 8; q++) {
        const int ch = tk*8 + q;
        float4 v = *(float4*)&zs[ch*260 + tp*4];
        float bias = sbias[ch];
        float a0 = v.x + bias, a1 = v.y + bias, a2 = v.z + bias, a3 = v.w + bias;
        sc[0][q] = a0;
        sc[1][q] = sc[0][q] + a1;
        sc[2][q] = sc[1][q] + a2;
        sc[3][q] = sc[2][q] + a3;
        float s = sc[3][q];
        #pragma unroll
        for (int o = 1; o < 32; o <<= 1) {
            float u = __shfl_up_sync(0xffffffffu, s, o);
            if (lane >= o) s += u;
        }
        tot[q] = s;
        if (lane == 31) wtot[wid*8 + q] = s;
    }
    __syncthreads();

    #pragma unroll
    for (int q = 0; q < 8; q++) {
        const int ch = tk*8 + q;
        float off = tot[q] - sc[3][q];            // exclusive within warp
        if (wid & 1) off += wtot[(wid - 1)*8 + q];
        float4 r = make_float4(sc[0][q] + off, sc[1][q] + off,
                               sc[2][q] + off, sc[3][q] + off);
        *(float4*)(g_z + (size_t)(b*BTC + ch)*HWSZ + ij + tp*4) = r;
    }
}

// ---------------------------------------------------------------------------
// Kernel 2pre: per-chunk column totals of row-scanned z.
// ---------------------------------------------------------------------------
__global__ __launch_bounds__(256) void k2pre_chunktot()
{
    const int chunk = blockIdx.x;
    const int plane = blockIdx.y;
    const int j     = threadIdx.x;
    const float* zp = g_z + (size_t)plane*HWSZ + (size_t)(chunk*64)*WW + j;

    float acc = 0.f;
    #pragma unroll 8
    for (int r = 0; r < 64; r++)
        acc += zp[(size_t)r*WW];
    g_ctot[plane][chunk][j] = acc;
}

// ---------------------------------------------------------------------------
// Kernel 2a: chunk column cumsum seeded with earlier-chunk prefix -> FINAL S.
// ---------------------------------------------------------------------------
__global__ __launch_bounds__(256) void k2a_colsum_chunk()
{
    const int chunk = blockIdx.x;
    const int plane = blockIdx.y;
    const int j     = threadIdx.x;
    const int r0    = chunk * 64;

    const float* zp = g_z + (size_t)plane*HWSZ + (size_t)r0*WW + j;
    float* Sp = g_S + (size_t)plane*SW*SW;

    if (chunk == 0) {
        Sp[j] = 0.f;
        if (j == 0) Sp[256] = 0.f;
    }
    if (j < 64)
        Sp[(size_t)(r0 + j + 1)*SW] = 0.f;

    float acc = 0.f;
    for (int p = 0; p < chunk; p++)
        acc += g_ctot[plane][p][j];

    #pragma unroll 8
    for (int r = 0; r < 64; r++) {
        acc += zp[(size_t)r*WW];
        Sp[(size_t)(r0 + r + 1)*SW + (j + 1)] = acc;
    }
}

// ---------------------------------------------------------------------------
// Kernel 3: separable box filter, row-march phase 1 (known-good ~70us).
// ---------------------------------------------------------------------------
__global__ __launch_bounds__(256) void k3_box(
    const float* __restrict__ x,
    const float* __restrict__ xmn_, const float* __restrict__ xmx_,
    const float* __restrict__ ymn_, const float* __restrict__ ymx_,
    const float* __restrict__ g2, const float* __restrict__ b2,
    const float* __restrict__ m2, const float* __restrict__ v2,
    float* __restrict__ out)
{
    __shared__ float Dv[8][SW];

    const int bid = blockIdx.x;
    const int rc  = bid & 31;
    const int nb  = (bid >> 5) & (NBOX-1);
    const int bt  = (bid >> 7) & (BTC-1);
    const int b   = bid >> 12;
    const int j   = threadIdx.x;
    const int k   = bt*NBOX + nb;
    const int boxi = bt*NBOX + nb;

    const float xmn = xmn_[boxi], xmx = xmx_[boxi];
    const float ymn = ymn_[boxi], ymx = ymx_[boxi];
    const float inv_area = 1.f / ((xmx - xmn) * (ymx - ymn));

    const float* Sp = g_S + (size_t)(b*BTC + bt)*SW*SW;

    const int i0 = rc*8;
    const float aA = (float)i0 + xmx;
    const float aB = (float)i0 + xmn;
    const float fAf = floorf(aA), fBf = floorf(aB);
    const int   rA0 = (int)fAf,  rB0 = (int)fBf;
    const float wA = aA - fAf,   wB = aB - fBf;

    #pragma unroll
    for (int half = 0; half < 2; half++) {
        int rh = half*4;
        float SA[5], SB[5];
        #pragma unroll
        for (int tt = 0; tt < 5; tt++) {
            int ra = rA0 + rh + tt;  ra = (ra > 256) ? 256 : ra;
            int rb = rB0 + rh + tt;  rb = (rb > 256) ? 256 : rb;
            SA[tt] = (ra < 0) ? 0.f : Sp[(size_t)ra*SW + j];
            SB[tt] = (rb < 0) ? 0.f : Sp[(size_t)rb*SW + j];
        }
        #pragma unroll
        for (int tt = 0; tt < 4; tt++)
            Dv[rh + tt][j] = (SA[tt]*(1.f-wA) + SA[tt+1]*wA)
                           - (SB[tt]*(1.f-wB) + SB[tt+1]*wB);
        if (j == 255) {
            float TA[5], TB[5];
            #pragma unroll
            for (int tt = 0; tt < 5; tt++) {
                int ra = rA0 + rh + tt;  ra = (ra > 256) ? 256 : ra;
                int rb = rB0 + rh + tt;  rb = (rb > 256) ? 256 : rb;
                TA[tt] = (ra < 0) ? 0.f : Sp[(size_t)ra*SW + 256];
                TB[tt] = (rb < 0) ? 0.f : Sp[(size_t)rb*SW + 256];
            }
            #pragma unroll
            for (int tt = 0; tt < 4; tt++)
                Dv[rh + tt][256] = (TA[tt]*(1.f-wA) + TA[tt+1]*wA)
                                 - (TB[tt]*(1.f-wB) + TB[tt+1]*wB);
        }
    }
    __syncthreads();

    float vA = fminf(fmaxf((float)j + ymx, 0.f), 256.f);
    float vB = fminf(fmaxf((float)j + ymn, 0.f), 256.f);
    float gA = fminf(floorf(vA), 255.f);
    float gB = fminf(floorf(vB), 255.f);
    int   jA = (int)gA, jB = (int)gB;
    float wvA = vA - gA, wvB = vB - gB;

    float inv2  = g2[k] * rsqrtf(v2[k] + 1e-3f);
    float bias2 = b2[k] - m2[k]*inv2;

    const float* xrow = x   + ((size_t)(b*CC + k)*HH + i0)*WW + j;
    float*       orow = out + ((size_t)(b*CC + k)*HH + i0)*WW + j;

    #pragma unroll
    for (int r = 0; r < 8; r++) {
        float DA = Dv[r][jA]*(1.f - wvA) + Dv[r][jA+1]*wvA;
        float DB = Dv[r][jB]*(1.f - wvB) + Dv[r][jB+1]*wvB;
        float val = (DA - DB) * inv_area;

        val = fmaxf(val*inv2 + bias2, 0.f);
        orow[(size_t)r*WW] = fmaxf(xrow[(size_t)r*WW] + val, 0.f);
    }
}

// ---------------------------------------------------------------------------
extern "C" void kernel_launch(void* const* d_in, const int* in_sizes, int n_in,
                              void* d_out, int out_size)
{
    const float* x    = (const float*)d_in[0];
    const float* w1   = (const float*)d_in[1];
    const float* g1   = (const float*)d_in[2];
    const float* b1   = (const float*)d_in[3];
    const float* m1   = (const float*)d_in[4];
    const float* v1   = (const float*)d_in[5];
    const float* xmn  = (const float*)d_in[6];
    const float* xmx  = (const float*)d_in[7];
    const float* ymn  = (const float*)d_in[8];
    const float* ymx  = (const float*)d_in[9];
    const float* g2   = (const float*)d_in[10];
    const float* b2   = (const float*)d_in[11];
    const float* m2   = (const float*)d_in[12];
    const float* v2   = (const float*)d_in[13];
    float* out = (float*)d_out;

    cudaFuncSetAttribute(k1_mma_rowscan,
                         cudaFuncAttributeMaxDynamicSharedMemorySize, SM_TOTAL);

    k1_mma_rowscan<<<(BB*HWSZ)/256, 256, SM_TOTAL>>>(x, w1, g1, b1, m1, v1);
    k2pre_chunktot<<<dim3(4, BB*BTC), 256>>>();
    k2a_colsum_chunk<<<dim3(4, BB*BTC), 256>>>();
    k3_box<<<BB*BTC*NBOX*(HH/8), 256>>>(x, xmn, xmx, ymn, ymx, g2, b2, m2, v2, out);
}